// round 11
// baseline (speedup 1.0000x reference)
#include <cuda_runtime.h>
#include <cuda_bf16.h>
#include <cstdint>
#include <math.h>

#define BATCH   8
#define NNODES  2048
#define FDIM    256
#define HEADS   4
#define HD      256
#define MTOT    (BATCH*NNODES)

// ---- scratch ----
__device__ float g_Wh[(size_t)MTOT * HD];           // Wh, tf32-rounded, [node][feat]
__device__ float g_e[MTOT * HEADS];
__device__ float g_att[MTOT];
__device__ __nv_bfloat16 g_W_hi[FDIM * HD];         // W^T pre-split: [n][k] bf16 hi
__device__ __nv_bfloat16 g_W_lo[FDIM * HD];         // [n][k] bf16 lo

// ================= helpers =================
__device__ __forceinline__ uint32_t smem_u32(const void* p) {
    uint32_t a;
    asm("{ .reg .u64 t; cvta.to.shared.u64 t, %1; cvt.u32.u64 %0, t; }" : "=r"(a) : "l"(p));
    return a;
}
__device__ __forceinline__ float tf32_rna(float x) {
    uint32_t u;
    asm("cvt.rna.tf32.f32 %0, %1;" : "=r"(u) : "f"(x));
    return __uint_as_float(u);
}
__device__ __forceinline__ void split2(float x, float y, uint32_t& hi, uint32_t& lo) {
    __nv_bfloat16 hx = __float2bfloat16_rn(x);
    __nv_bfloat16 hy = __float2bfloat16_rn(y);
    __nv_bfloat16 lx = __float2bfloat16_rn(x - __bfloat162float(hx));
    __nv_bfloat16 ly = __float2bfloat16_rn(y - __bfloat162float(hy));
    __nv_bfloat162 H; H.x = hx; H.y = hy;
    __nv_bfloat162 L; L.x = lx; L.y = ly;
    hi = *(uint32_t*)&H;
    lo = *(uint32_t*)&L;
}
// swizzled byte offset within an N-row x 64B tile (rows of 4x16B units)
__device__ __forceinline__ uint32_t swa(int row, int u) {
    return (uint32_t)(row * 64 + (((u ^ ((row >> 1) & 3))) << 4));
}
__device__ __forceinline__ uint32_t fragaddr(uint32_t base, int row_base, int lane, int u0) {
    int r = row_base + (lane & 15);
    int u = u0 + (lane >> 4);
    return base + swa(r, u);
}

#define LDSM4(r, a) \
    asm volatile("ldmatrix.sync.aligned.m8n8.x4.shared.b16 {%0,%1,%2,%3}, [%4];" \
        : "=r"((r)[0]), "=r"((r)[1]), "=r"((r)[2]), "=r"((r)[3]) : "r"(a))

#define MMA16816(c, a, b0, b1) \
    asm volatile("mma.sync.aligned.m16n8k16.row.col.f32.bf16.bf16.f32 " \
        "{%0,%1,%2,%3}, {%4,%5,%6,%7}, {%8,%9}, {%0,%1,%2,%3};" \
        : "+f"((c)[0]), "+f"((c)[1]), "+f"((c)[2]), "+f"((c)[3]) \
        : "r"((a)[0]), "r"((a)[1]), "r"((a)[2]), "r"((a)[3]), "r"(b0), "r"(b1))

#define MMA1688(c, a, b0, b1) \
    asm volatile("mma.sync.aligned.m16n8k8.row.col.f32.tf32.tf32.f32 " \
        "{%0,%1,%2,%3}, {%4,%5,%6,%7}, {%8,%9}, {%0,%1,%2,%3};" \
        : "+f"((c)[0]), "+f"((c)[1]), "+f"((c)[2]), "+f"((c)[3]) \
        : "r"((a)[0]), "r"((a)[1]), "r"((a)[2]), "r"((a)[3]), "r"(b0), "r"(b1))

#define CPASYNC16(dst, src) \
    asm volatile("cp.async.ca.shared.global [%0], [%1], 16;" :: "r"(dst), "l"(src))
#define CPCOMMIT() asm volatile("cp.async.commit_group;")
#define CPWAIT0()  asm volatile("cp.async.wait_group 0;")

// ============================================================
// Kernel W-split: one-time W[k][n] -> transposed bf16 hi/lo [n][k]
// ============================================================
__global__ __launch_bounds__(256) void k_wsplit(const float* __restrict__ W) {
    int id = blockIdx.x * 256 + threadIdx.x;     // 65536
    int k = id >> 8, n = id & 255;
    float v = W[k * HD + n];                     // coalesced read
    __nv_bfloat16 h = __float2bfloat16_rn(v);
    __nv_bfloat16 l = __float2bfloat16_rn(v - __bfloat162float(h));
    g_W_hi[n * FDIM + k] = h;
    g_W_lo[n * FDIM + k] = l;
}

// ============================================================
// Kernel A: Wh = X @ W via bf16x3 mma.sync (R3-proven pattern)
// BM=128, BN=64 (one head), BK=32, 8 warps (4m x 2n), double-buffered
// e computed from fp32 accumulators (err ~1e-4 on att, negligible)
// ============================================================
#define WA_HI  0
#define WA_LO  8192
#define WB_HI  16384
#define WB_LO  20480
#define WSTAGE 24576

__global__ void __launch_bounds__(256)
k_wh_mma(const float* __restrict__ X) {
    extern __shared__ char smem[];
    __shared__ float esh[128][4];
    const uint32_t sb = smem_u32(smem);
    const int t    = threadIdx.x;
    const int lane = t & 31;
    const int wid  = t >> 5;
    const int head = blockIdx.x;
    const int m0   = blockIdx.y * 128;
    const int warp_m = wid & 3;   // 32 rows
    const int warp_n = wid >> 2;  // 32 cols

    const __nv_bfloat16* BhG = g_W_hi + (size_t)(head * 64) * FDIM;
    const __nv_bfloat16* BlG = g_W_lo + (size_t)(head * 64) * FDIM;

    float c[2][4][4];
    #pragma unroll
    for (int mt = 0; mt < 2; mt++)
        #pragma unroll
        for (int nt = 0; nt < 4; nt++)
            #pragma unroll
            for (int j = 0; j < 4; j++) c[mt][nt][j] = 0.f;

    float4 pa[2][2];

    // ---- prologue: tile 0 ----
    #pragma unroll
    for (int it = 0; it < 2; it++) {
        int idx = t + it * 256, row = idx >> 2, cc = idx & 3;
        const float* p = X + (size_t)(m0 + row) * FDIM + cc * 8;
        pa[it][0] = *(const float4*)p;
        pa[it][1] = *(const float4*)(p + 4);
    }
    {
        int row = t >> 2, u = t & 3;
        size_t g = (size_t)row * FDIM + u * 8;
        CPASYNC16(sb + WB_HI + swa(row, u), BhG + g);
        CPASYNC16(sb + WB_LO + swa(row, u), BlG + g);
    }
    CPCOMMIT();
    #pragma unroll
    for (int it = 0; it < 2; it++) {
        int idx = t + it * 256, row = idx >> 2, cc = idx & 3;
        float f[8] = {pa[it][0].x, pa[it][0].y, pa[it][0].z, pa[it][0].w,
                      pa[it][1].x, pa[it][1].y, pa[it][1].z, pa[it][1].w};
        uint32_t hi[4], lo[4];
        #pragma unroll
        for (int j = 0; j < 4; j++) split2(f[2*j], f[2*j+1], hi[j], lo[j]);
        uint32_t off = swa(row, cc);
        *(uint4*)(smem + WA_HI + off) = make_uint4(hi[0], hi[1], hi[2], hi[3]);
        *(uint4*)(smem + WA_LO + off) = make_uint4(lo[0], lo[1], lo[2], lo[3]);
    }
    CPWAIT0();
    __syncthreads();

    // ---- main loop: 8 k-tiles ----
    for (int i = 0; i < 8; i++) {
        const uint32_t cur = sb + (uint32_t)(i & 1) * WSTAGE;

        if (i < 7) {
            const int k0 = (i + 1) * 32;
            #pragma unroll
            for (int it = 0; it < 2; it++) {
                int idx = t + it * 256, row = idx >> 2, cc = idx & 3;
                const float* p = X + (size_t)(m0 + row) * FDIM + k0 + cc * 8;
                pa[it][0] = *(const float4*)p;
                pa[it][1] = *(const float4*)(p + 4);
            }
            const uint32_t nxt = sb + (uint32_t)((i + 1) & 1) * WSTAGE;
            {
                int row = t >> 2, u = t & 3;
                size_t g = (size_t)row * FDIM + k0 + u * 8;
                CPASYNC16(nxt + WB_HI + swa(row, u), BhG + g);
                CPASYNC16(nxt + WB_LO + swa(row, u), BlG + g);
            }
            CPCOMMIT();
        }

        #pragma unroll
        for (int kk = 0; kk < 2; kk++) {
            uint32_t ahi[2][4], alo[2][4];
            #pragma unroll
            for (int mt = 0; mt < 2; mt++) {
                LDSM4(ahi[mt], fragaddr(cur + WA_HI, warp_m*32 + mt*16, lane, kk*2));
                LDSM4(alo[mt], fragaddr(cur + WA_LO, warp_m*32 + mt*16, lane, kk*2));
            }
            #pragma unroll
            for (int ng = 0; ng < 2; ng++) {
                uint32_t bhi[4], blo[4];
                LDSM4(bhi, fragaddr(cur + WB_HI, warp_n*32 + ng*16, lane, kk*2));
                LDSM4(blo, fragaddr(cur + WB_LO, warp_n*32 + ng*16, lane, kk*2));
                #pragma unroll
                for (int mt = 0; mt < 2; mt++) {
                    MMA16816(c[mt][2*ng],   ahi[mt], bhi[0], bhi[2]);
                    MMA16816(c[mt][2*ng],   ahi[mt], blo[0], blo[2]);
                    MMA16816(c[mt][2*ng],   alo[mt], bhi[0], bhi[2]);
                    MMA16816(c[mt][2*ng+1], ahi[mt], bhi[1], bhi[3]);
                    MMA16816(c[mt][2*ng+1], ahi[mt], blo[1], blo[3]);
                    MMA16816(c[mt][2*ng+1], alo[mt], bhi[1], bhi[3]);
                }
            }
        }

        if (i < 7) {
            char* nsp = smem + ((i + 1) & 1) * WSTAGE;
            #pragma unroll
            for (int it = 0; it < 2; it++) {
                int idx = t + it * 256, row = idx >> 2, cc = idx & 3;
                float f[8] = {pa[it][0].x, pa[it][0].y, pa[it][0].z, pa[it][0].w,
                              pa[it][1].x, pa[it][1].y, pa[it][1].z, pa[it][1].w};
                uint32_t hi[4], lo[4];
                #pragma unroll
                for (int j = 0; j < 4; j++) split2(f[2*j], f[2*j+1], hi[j], lo[j]);
                uint32_t off = swa(row, cc);
                *(uint4*)(nsp + WA_HI + off) = make_uint4(hi[0], hi[1], hi[2], hi[3]);
                *(uint4*)(nsp + WA_LO + off) = make_uint4(lo[0], lo[1], lo[2], lo[3]);
            }
            CPWAIT0();
            __syncthreads();
        }
    }

    // ---- epilogue: write Wh (tf32-rounded) + e partials ----
    #pragma unroll
    for (int mt = 0; mt < 2; mt++) {
        int r0 = m0 + warp_m * 32 + mt * 16 + (lane >> 2);
        float* o0 = g_Wh + (size_t)r0 * HD;
        float* o1 = o0 + (size_t)8 * HD;
        float s0 = 0.f, s1 = 0.f;
        #pragma unroll
        for (int nt = 0; nt < 4; nt++) {
            int col = head * 64 + warp_n * 32 + nt * 8 + 2 * (lane & 3);
            float2 v0, v1;
            v0.x = tf32_rna(c[mt][nt][0]); v0.y = tf32_rna(c[mt][nt][1]);
            v1.x = tf32_rna(c[mt][nt][2]); v1.y = tf32_rna(c[mt][nt][3]);
            *(float2*)(o0 + col) = v0;
            *(float2*)(o1 + col) = v1;
            s0 += c[mt][nt][0]*c[mt][nt][0] + c[mt][nt][1]*c[mt][nt][1];
            s1 += c[mt][nt][2]*c[mt][nt][2] + c[mt][nt][3]*c[mt][nt][3];
        }
        s0 += __shfl_xor_sync(0xffffffffu, s0, 1);
        s0 += __shfl_xor_sync(0xffffffffu, s0, 2);
        s1 += __shfl_xor_sync(0xffffffffu, s1, 1);
        s1 += __shfl_xor_sync(0xffffffffu, s1, 2);
        if ((lane & 3) == 0) {
            int rl = warp_m * 32 + mt * 16 + (lane >> 2);
            esh[rl][warp_n]     = s0;
            esh[rl + 8][warp_n] = s1;
        }
    }
    __syncthreads();
    if (t < 128)
        g_e[(size_t)(m0 + t) * HEADS + head] = esh[t][0] + esh[t][1];
}

// ============================================================
// Kernel B: fused softmax stats + head-mean attention (one block / batch)
// ============================================================
__global__ __launch_bounds__(256) void k_soft_att() {
    const int b = blockIdx.x;
    const int t = threadIdx.x;
    __shared__ float red[256];
    __shared__ float s_mx[HEADS], s_inv[HEADS];

    const float* eb = g_e + (size_t)b * NNODES * HEADS;

    for (int h = 0; h < HEADS; h++) {
        float mx = -1e30f;
        for (int n = t; n < NNODES; n += 256)
            mx = fmaxf(mx, eb[n * HEADS + h]);
        red[t] = mx; __syncthreads();
        for (int s = 128; s > 0; s >>= 1) {
            if (t < s) red[t] = fmaxf(red[t], red[t + s]);
            __syncthreads();
        }
        mx = red[0]; __syncthreads();

        float sum = 0.f;
        for (int n = t; n < NNODES; n += 256)
            sum += __expf(eb[n * HEADS + h] - mx);
        red[t] = sum; __syncthreads();
        for (int s = 128; s > 0; s >>= 1) {
            if (t < s) red[t] += red[t + s];
            __syncthreads();
        }
        if (t == 0) { s_mx[h] = mx; s_inv[h] = 1.0f / red[0]; }
        __syncthreads();
    }

    for (int n = t; n < NNODES; n += 256) {
        float a = 0.f;
        #pragma unroll
        for (int h = 0; h < HEADS; h++)
            a += __expf(eb[n * HEADS + h] - s_mx[h]) * s_inv[h];
        g_att[b * NNODES + n] = 0.25f * a;
    }
}

// ============================================================
// Kernel C: single-pass tf32 mma.sync GEMM  (EXACT R8 configuration)
// ============================================================
#define A_LD   36
#define B_LD   72
#define B_OFF  18432
#define STAGE  27648

__global__ void __launch_bounds__(256)
k_out_tf32(const float* __restrict__ adj, const float* __restrict__ bias,
           float* __restrict__ out) {
    extern __shared__ char smem[];
    const uint32_t sb = smem_u32(smem);
    const int t    = threadIdx.x;
    const int lane = t & 31;
    const int wid  = t >> 5;
    const int b    = blockIdx.z;
    const int n0   = blockIdx.x * 64;
    const int m0   = blockIdx.y * 128;
    const int warp_m = wid & 3;
    const int warp_n = wid >> 2;

    const float* adjb = adj + (size_t)b * NNODES * NNODES;
    const float* Whb  = g_Wh + ((size_t)b * NNODES) * HD;

    float c[2][4][4];
    #pragma unroll
    for (int mt = 0; mt < 2; mt++)
        #pragma unroll
        for (int nt = 0; nt < 4; nt++)
            #pragma unroll
            for (int j = 0; j < 4; j++) c[mt][nt][j] = 0.f;

    auto load_stage = [&](int k0, uint32_t dst) {
        #pragma unroll
        for (int it = 0; it < 4; it++) {
            int idx = t + it * 256;
            int row = idx >> 3, u = idx & 7;
            CPASYNC16(dst + row * (A_LD*4) + u * 16,
                      adjb + (size_t)(m0 + row) * NNODES + k0 + u * 4);
        }
        #pragma unroll
        for (int it = 0; it < 2; it++) {
            int idx = t + it * 256;
            int row = idx >> 4, u = idx & 15;
            CPASYNC16(dst + B_OFF + row * (B_LD*4) + u * 16,
                      Whb + (size_t)(k0 + row) * HD + n0 + u * 4);
        }
        CPCOMMIT();
    };

    load_stage(0, sb);
    CPWAIT0();
    __syncthreads();

    for (int i = 0; i < 64; i++) {
        const uint32_t cur = (uint32_t)(i & 1) * STAGE;
        if (i < 63) load_stage((i + 1) * 32, sb + (uint32_t)((i + 1) & 1) * STAGE);

        const float* Asm = (const float*)(smem + cur);
        const float* Bsm = (const float*)(smem + cur + B_OFF);

        #pragma unroll
        for (int s = 0; s < 4; s++) {
            const int kk = s * 8 + (lane & 3);
            uint32_t a[2][4];
            #pragma unroll
            for (int mt = 0; mt < 2; mt++) {
                int r = warp_m * 32 + mt * 16 + (lane >> 2);
                a[mt][0] = __float_as_uint(Asm[r * A_LD + kk]);
                a[mt][1] = __float_as_uint(Asm[(r + 8) * A_LD + kk]);
                a[mt][2] = __float_as_uint(Asm[r * A_LD + kk + 4]);
                a[mt][3] = __float_as_uint(Asm[(r + 8) * A_LD + kk + 4]);
            }
            #pragma unroll
            for (int ng = 0; ng < 4; ng++) {
                int n = warp_n * 32 + ng * 8 + (lane >> 2);
                uint32_t b0 = __float_as_uint(Bsm[kk * B_LD + n]);
                uint32_t b1 = __float_as_uint(Bsm[(kk + 4) * B_LD + n]);
                MMA1688(c[0][ng], a[0], b0, b1);
                MMA1688(c[1][ng], a[1], b0, b1);
            }
        }

        if (i < 63) { CPWAIT0(); __syncthreads(); }
    }

    #pragma unroll
    for (int mt = 0; mt < 2; mt++) {
        int r0 = m0 + warp_m * 32 + mt * 16 + (lane >> 2);
        float att0 = g_att[b * NNODES + r0];
        float att1 = g_att[b * NNODES + r0 + 8];
        float* o0 = out + ((size_t)(b * NNODES + r0)) * HD;
        float* o1 = o0 + (size_t)8 * HD;
        #pragma unroll
        for (int nt = 0; nt < 4; nt++) {
            int col = n0 + warp_n * 32 + nt * 8 + 2 * (lane & 3);
            float2 bv = *(const float2*)(bias + col);
            float2 v0, v1;
            v0.x = fmaxf(fmaf(att0, c[mt][nt][0], bv.x), 0.f);
            v0.y = fmaxf(fmaf(att0, c[mt][nt][1], bv.y), 0.f);
            v1.x = fmaxf(fmaf(att1, c[mt][nt][2], bv.x), 0.f);
            v1.y = fmaxf(fmaf(att1, c[mt][nt][3], bv.y), 0.f);
            *(float2*)(o0 + col) = v0;
            *(float2*)(o1 + col) = v1;
        }
    }
}

// ============================================================
extern "C" void kernel_launch(void* const* d_in, const int* in_sizes, int n_in,
                              void* d_out, int out_size) {
    const float* features = (const float*)d_in[0];   // [8,2048,256]
    const float* adj      = (const float*)d_in[1];   // [8,2048,2048]
    const float* W        = (const float*)d_in[2];   // [256,256]
    const float* bias     = (const float*)d_in[3];   // [256]
    float* out = (float*)d_out;                      // [8,2048,256]

    cudaFuncSetAttribute(k_wh_mma,  cudaFuncAttributeMaxDynamicSharedMemorySize, 2 * WSTAGE);
    cudaFuncSetAttribute(k_out_tf32, cudaFuncAttributeMaxDynamicSharedMemorySize, 2 * STAGE);

    k_wsplit  <<<FDIM * HD / 256, 256>>>(W);
    k_wh_mma  <<<dim3(HEADS, MTOT/128), 256, 2 * WSTAGE>>>(features);
    k_soft_att<<<BATCH, 256>>>();
    k_out_tf32<<<dim3(HD/64, NNODES/128, BATCH), 256, 2 * STAGE>>>(adj, bias, out);
}

// round 12
// speedup vs baseline: 1.3385x; 1.3385x over previous
#include <cuda_runtime.h>
#include <cstdint>
#include <math.h>

#define BATCH   8
#define NNODES  2048
#define FDIM    256
#define HEADS   4
#define HD      256
#define MTOT    (BATCH*NNODES)

// ---- scratch ----
__device__ float g_Wh[(size_t)MTOT * HD];   // Wh, tf32-rounded, natural [node][feat]
__device__ float g_e[MTOT * HEADS];
__device__ float g_att[MTOT];
__device__ float g_mx[BATCH * HEADS];
__device__ float g_inv[BATCH * HEADS];

// ================= helpers =================
__device__ __forceinline__ uint32_t smem_u32(const void* p) {
    uint32_t a;
    asm("{ .reg .u64 t; cvta.to.shared.u64 t, %1; cvt.u32.u64 %0, t; }" : "=r"(a) : "l"(p));
    return a;
}
__device__ __forceinline__ float tf32_rna(float x) {
    uint32_t u;
    asm("cvt.rna.tf32.f32 %0, %1;" : "=r"(u) : "f"(x));
    return __uint_as_float(u);
}

#define MMA1688(c, a, b0, b1) \
    asm volatile("mma.sync.aligned.m16n8k8.row.col.f32.tf32.tf32.f32 " \
        "{%0,%1,%2,%3}, {%4,%5,%6,%7}, {%8,%9}, {%0,%1,%2,%3};" \
        : "+f"((c)[0]), "+f"((c)[1]), "+f"((c)[2]), "+f"((c)[3]) \
        : "r"((a)[0]), "r"((a)[1]), "r"((a)[2]), "r"((a)[3]), "r"(b0), "r"(b1))

#define CPASYNC16(dst, src) \
    asm volatile("cp.async.ca.shared.global [%0], [%1], 16;" :: "r"(dst), "l"(src))
#define CPASYNC16CG(dst, src) \
    asm volatile("cp.async.cg.shared.global [%0], [%1], 16;" :: "r"(dst), "l"(src))
#define CPCOMMIT() asm volatile("cp.async.commit_group;")
#define CPWAIT0()  asm volatile("cp.async.wait_group 0;")

// ============================================================
// Kernel A: Wh = X @ W (fp32 SIMT, exact for e); double-buffered stages.
// BM=64, BN=64, BK=16, 256 threads, 4x4 microtile (R10-verified).
// ============================================================
__global__ __launch_bounds__(256) void k_wh(const float* __restrict__ X,
                                            const float* __restrict__ W) {
    __shared__ float As[2][16][68];
    __shared__ float Bs[2][16][68];
    __shared__ float esh[64][17];

    const int t    = threadIdx.x;
    const int m0   = blockIdx.y * 64;
    const int n0   = blockIdx.x * 64;
    const int trow = t >> 4;
    const int tcol = t & 15;

    const int xi = t >> 2;
    const int xq = t & 3;
    const int wk = t >> 4;
    const int wj = (t & 15) << 2;

    float acc[4][4] = {};

    auto ldgX = [&](int k0) -> float4 {
        return *(const float4*)(X + (size_t)(m0 + xi) * FDIM + k0 + xq * 4);
    };
    auto stsX = [&](float4 v, int s) {
        As[s][xq*4+0][xi] = v.x; As[s][xq*4+1][xi] = v.y;
        As[s][xq*4+2][xi] = v.z; As[s][xq*4+3][xi] = v.w;
    };
    auto cpB = [&](int k0, int s) {
        CPASYNC16(smem_u32(&Bs[s][wk][wj]), W + (size_t)(k0 + wk) * HD + n0 + wj);
        CPCOMMIT();
    };

    {
        float4 v0 = ldgX(0);
        cpB(0, 0);
        stsX(v0, 0);
        CPWAIT0();
        __syncthreads();
    }

    for (int kt = 0; kt < 16; kt++) {
        const int cur = kt & 1;
        float4 nv;
        if (kt < 15) { nv = ldgX((kt + 1) * 16); cpB((kt + 1) * 16, cur ^ 1); }

        #pragma unroll
        for (int k = 0; k < 16; k++) {
            float a[4], b[4];
            #pragma unroll
            for (int i = 0; i < 4; i++) a[i] = As[cur][k][trow*4 + i];
            #pragma unroll
            for (int j = 0; j < 4; j++) b[j] = Bs[cur][k][tcol*4 + j];
            #pragma unroll
            for (int i = 0; i < 4; i++)
                #pragma unroll
                for (int j = 0; j < 4; j++)
                    acc[i][j] = fmaf(a[i], b[j], acc[i][j]);
        }
        __syncthreads();
        if (kt < 15) {
            stsX(nv, cur ^ 1);
            CPWAIT0();
            __syncthreads();
        }
    }

    #pragma unroll
    for (int i = 0; i < 4; i++) {
        int m = m0 + trow * 4 + i;
        float4 o;
        o.x = tf32_rna(acc[i][0]); o.y = tf32_rna(acc[i][1]);
        o.z = tf32_rna(acc[i][2]); o.w = tf32_rna(acc[i][3]);
        *(float4*)(g_Wh + (size_t)m * HD + n0 + tcol * 4) = o;
    }

    #pragma unroll
    for (int i = 0; i < 4; i++) {
        float s = acc[i][0]*acc[i][0] + acc[i][1]*acc[i][1]
                + acc[i][2]*acc[i][2] + acc[i][3]*acc[i][3];
        esh[trow*4 + i][tcol] = s;
    }
    __syncthreads();
    if (t < 64) {
        float s = 0.f;
        #pragma unroll
        for (int j = 0; j < 16; j++) s += esh[t][j];
        g_e[(size_t)(m0 + t) * HEADS + (n0 >> 6)] = s;
    }
}

// ============================================================
// Kernel B1: per-(b,h) softmax stats — 32 blocks
// ============================================================
__global__ __launch_bounds__(256) void k_stats() {
    const int b = blockIdx.x >> 2;
    const int h = blockIdx.x & 3;
    const int t = threadIdx.x;
    __shared__ float red[256];

    const float* eb = g_e + (size_t)b * NNODES * HEADS;

    float mx = -1e30f;
    for (int n = t; n < NNODES; n += 256)
        mx = fmaxf(mx, eb[n * HEADS + h]);
    red[t] = mx; __syncthreads();
    for (int s = 128; s > 0; s >>= 1) {
        if (t < s) red[t] = fmaxf(red[t], red[t + s]);
        __syncthreads();
    }
    mx = red[0]; __syncthreads();

    float sum = 0.f;
    for (int n = t; n < NNODES; n += 256)
        sum += __expf(eb[n * HEADS + h] - mx);
    red[t] = sum; __syncthreads();
    for (int s = 128; s > 0; s >>= 1) {
        if (t < s) red[t] += red[t + s];
        __syncthreads();
    }
    if (t == 0) {
        g_mx[blockIdx.x]  = mx;
        g_inv[blockIdx.x] = 1.0f / red[0];
    }
}

// ============================================================
// Kernel B2: att = head-mean of softmax — 64 blocks
// ============================================================
__global__ __launch_bounds__(256) void k_att() {
    int m = blockIdx.x * 256 + threadIdx.x;
    if (m >= MTOT) return;
    int b = m >> 11;
    const float* e4 = g_e + (size_t)m * HEADS;
    float a = 0.f;
    #pragma unroll
    for (int h = 0; h < HEADS; h++)
        a += __expf(e4[h] - g_mx[b * HEADS + h]) * g_inv[b * HEADS + h];
    g_att[m] = 0.25f * a;
}

// ============================================================
// Kernel C: single-pass tf32 mma.sync GEMM  (R8/R10-verified shape)
//   out = relu(att*(adj @ Wh) + bias)
// BM=128, BN=64, BK=32, 8 warps (4m x 2n), double-buffered cp.async.cg
// A raw fp32 bits (HW tf32 trunc); A [128][36], B [32][72] — conflict-free
// ============================================================
#define A_LD   36
#define B_LD   72
#define B_OFF  18432
#define STAGE  27648

__global__ void __launch_bounds__(256)
k_out_tf32(const float* __restrict__ adj, const float* __restrict__ bias,
           float* __restrict__ out) {
    extern __shared__ char smem[];
    const uint32_t sb = smem_u32(smem);
    const int t    = threadIdx.x;
    const int lane = t & 31;
    const int wid  = t >> 5;
    const int b    = blockIdx.z;
    const int n0   = blockIdx.x * 64;
    const int m0   = blockIdx.y * 128;
    const int warp_m = wid & 3;
    const int warp_n = wid >> 2;

    const float* adjb = adj + (size_t)b * NNODES * NNODES;
    const float* Whb  = g_Wh + ((size_t)b * NNODES) * HD;

    float c[2][4][4];
    #pragma unroll
    for (int mt = 0; mt < 2; mt++)
        #pragma unroll
        for (int nt = 0; nt < 4; nt++)
            #pragma unroll
            for (int j = 0; j < 4; j++) c[mt][nt][j] = 0.f;

    auto load_stage = [&](int k0, uint32_t dst) {
        #pragma unroll
        for (int it = 0; it < 4; it++) {
            int idx = t + it * 256;
            int row = idx >> 3, u = idx & 7;
            CPASYNC16CG(dst + row * (A_LD*4) + u * 16,
                        adjb + (size_t)(m0 + row) * NNODES + k0 + u * 4);
        }
        #pragma unroll
        for (int it = 0; it < 2; it++) {
            int idx = t + it * 256;
            int row = idx >> 4, u = idx & 15;
            CPASYNC16CG(dst + B_OFF + row * (B_LD*4) + u * 16,
                        Whb + (size_t)(k0 + row) * HD + n0 + u * 4);
        }
        CPCOMMIT();
    };

    load_stage(0, sb);
    CPWAIT0();
    __syncthreads();

    for (int i = 0; i < 64; i++) {
        const uint32_t cur = (uint32_t)(i & 1) * STAGE;
        if (i < 63) load_stage((i + 1) * 32, sb + (uint32_t)((i + 1) & 1) * STAGE);

        const float* Asm = (const float*)(smem + cur);
        const float* Bsm = (const float*)(smem + cur + B_OFF);

        #pragma unroll
        for (int s = 0; s < 4; s++) {
            const int kk = s * 8 + (lane & 3);
            uint32_t a[2][4];
            #pragma unroll
            for (int mt = 0; mt < 2; mt++) {
                int r = warp_m * 32 + mt * 16 + (lane >> 2);
                a[mt][0] = __float_as_uint(Asm[r * A_LD + kk]);
                a[mt][1] = __float_as_uint(Asm[(r + 8) * A_LD + kk]);
                a[mt][2] = __float_as_uint(Asm[r * A_LD + kk + 4]);
                a[mt][3] = __float_as_uint(Asm[(r + 8) * A_LD + kk + 4]);
            }
            #pragma unroll
            for (int ng = 0; ng < 4; ng++) {
                int n = warp_n * 32 + ng * 8 + (lane >> 2);
                uint32_t b0 = __float_as_uint(Bsm[kk * B_LD + n]);
                uint32_t b1 = __float_as_uint(Bsm[(kk + 4) * B_LD + n]);
                MMA1688(c[0][ng], a[0], b0, b1);
                MMA1688(c[1][ng], a[1], b0, b1);
            }
        }

        if (i < 63) { CPWAIT0(); __syncthreads(); }
    }

    #pragma unroll
    for (int mt = 0; mt < 2; mt++) {
        int r0 = m0 + warp_m * 32 + mt * 16 + (lane >> 2);
        float att0 = g_att[b * NNODES + r0];
        float att1 = g_att[b * NNODES + r0 + 8];
        float* o0 = out + ((size_t)(b * NNODES + r0)) * HD;
        float* o1 = o0 + (size_t)8 * HD;
        #pragma unroll
        for (int nt = 0; nt < 4; nt++) {
            int col = n0 + warp_n * 32 + nt * 8 + 2 * (lane & 3);
            float2 bv = *(const float2*)(bias + col);
            float2 v0, v1;
            v0.x = fmaxf(fmaf(att0, c[mt][nt][0], bv.x), 0.f);
            v0.y = fmaxf(fmaf(att0, c[mt][nt][1], bv.y), 0.f);
            v1.x = fmaxf(fmaf(att1, c[mt][nt][2], bv.x), 0.f);
            v1.y = fmaxf(fmaf(att1, c[mt][nt][3], bv.y), 0.f);
            *(float2*)(o0 + col) = v0;
            *(float2*)(o1 + col) = v1;
        }
    }
}

// ============================================================
extern "C" void kernel_launch(void* const* d_in, const int* in_sizes, int n_in,
                              void* d_out, int out_size) {
    const float* features = (const float*)d_in[0];   // [8,2048,256]
    const float* adj      = (const float*)d_in[1];   // [8,2048,2048]
    const float* W        = (const float*)d_in[2];   // [256,256]
    const float* bias     = (const float*)d_in[3];   // [256]
    float* out = (float*)d_out;                      // [8,2048,256]

    cudaFuncSetAttribute(k_out_tf32, cudaFuncAttributeMaxDynamicSharedMemorySize, 2 * STAGE);

    k_wh      <<<dim3(HD/64, MTOT/64), 256>>>(features, W);
    k_stats   <<<BATCH*HEADS, 256>>>();
    k_att     <<<MTOT/256, 256>>>();
    k_out_tf32<<<dim3(HD/64, NNODES/128, BATCH), 256, 2 * STAGE>>>(adj, bias, out);
}

// round 13
// speedup vs baseline: 1.5781x; 1.1790x over previous
#include <cuda_runtime.h>
#include <cstdint>
#include <math.h>

#define BATCH   8
#define NNODES  2048
#define FDIM    256
#define HEADS   4
#define HD      256
#define MTOT    (BATCH*NNODES)

// ---- scratch ----
__device__ float g_Wh[(size_t)MTOT * HD];   // Wh, tf32-rounded, natural [node][feat]
__device__ float g_e[MTOT * HEADS];
__device__ float g_att[MTOT];
__device__ float g_mx[BATCH * HEADS];
__device__ float g_inv[BATCH * HEADS];

// ================= helpers =================
__device__ __forceinline__ uint32_t smem_u32(const void* p) {
    uint32_t a;
    asm("{ .reg .u64 t; cvta.to.shared.u64 t, %1; cvt.u32.u64 %0, t; }" : "=r"(a) : "l"(p));
    return a;
}
__device__ __forceinline__ float tf32_rna(float x) {
    uint32_t u;
    asm("cvt.rna.tf32.f32 %0, %1;" : "=r"(u) : "f"(x));
    return __uint_as_float(u);
}

#define MMA1688(c, a, b0, b1) \
    asm volatile("mma.sync.aligned.m16n8k8.row.col.f32.tf32.tf32.f32 " \
        "{%0,%1,%2,%3}, {%4,%5,%6,%7}, {%8,%9}, {%0,%1,%2,%3};" \
        : "+f"((c)[0]), "+f"((c)[1]), "+f"((c)[2]), "+f"((c)[3]) \
        : "r"((a)[0]), "r"((a)[1]), "r"((a)[2]), "r"((a)[3]), "r"(b0), "r"(b1))

#define CPASYNC16(dst, src) \
    asm volatile("cp.async.ca.shared.global [%0], [%1], 16;" :: "r"(dst), "l"(src))
#define CPASYNC16CG(dst, src) \
    asm volatile("cp.async.cg.shared.global [%0], [%1], 16;" :: "r"(dst), "l"(src))
#define CPCOMMIT() asm volatile("cp.async.commit_group;")
#define CPWAIT0()  asm volatile("cp.async.wait_group 0;")

// ============================================================
// Kernel A: Wh = X @ W (fp32 SIMT, exact for e); double-buffered (R10-verified)
// ============================================================
__global__ __launch_bounds__(256) void k_wh(const float* __restrict__ X,
                                            const float* __restrict__ W) {
    __shared__ float As[2][16][68];
    __shared__ float Bs[2][16][68];
    __shared__ float esh[64][17];

    const int t    = threadIdx.x;
    const int m0   = blockIdx.y * 64;
    const int n0   = blockIdx.x * 64;
    const int trow = t >> 4;
    const int tcol = t & 15;

    const int xi = t >> 2;
    const int xq = t & 3;
    const int wk = t >> 4;
    const int wj = (t & 15) << 2;

    float acc[4][4] = {};

    auto ldgX = [&](int k0) -> float4 {
        return *(const float4*)(X + (size_t)(m0 + xi) * FDIM + k0 + xq * 4);
    };
    auto stsX = [&](float4 v, int s) {
        As[s][xq*4+0][xi] = v.x; As[s][xq*4+1][xi] = v.y;
        As[s][xq*4+2][xi] = v.z; As[s][xq*4+3][xi] = v.w;
    };
    auto cpB = [&](int k0, int s) {
        CPASYNC16(smem_u32(&Bs[s][wk][wj]), W + (size_t)(k0 + wk) * HD + n0 + wj);
        CPCOMMIT();
    };

    {
        float4 v0 = ldgX(0);
        cpB(0, 0);
        stsX(v0, 0);
        CPWAIT0();
        __syncthreads();
    }

    for (int kt = 0; kt < 16; kt++) {
        const int cur = kt & 1;
        float4 nv;
        if (kt < 15) { nv = ldgX((kt + 1) * 16); cpB((kt + 1) * 16, cur ^ 1); }

        #pragma unroll
        for (int k = 0; k < 16; k++) {
            float a[4], b[4];
            #pragma unroll
            for (int i = 0; i < 4; i++) a[i] = As[cur][k][trow*4 + i];
            #pragma unroll
            for (int j = 0; j < 4; j++) b[j] = Bs[cur][k][tcol*4 + j];
            #pragma unroll
            for (int i = 0; i < 4; i++)
                #pragma unroll
                for (int j = 0; j < 4; j++)
                    acc[i][j] = fmaf(a[i], b[j], acc[i][j]);
        }
        __syncthreads();
        if (kt < 15) {
            stsX(nv, cur ^ 1);
            CPWAIT0();
            __syncthreads();
        }
    }

    #pragma unroll
    for (int i = 0; i < 4; i++) {
        int m = m0 + trow * 4 + i;
        float4 o;
        o.x = tf32_rna(acc[i][0]); o.y = tf32_rna(acc[i][1]);
        o.z = tf32_rna(acc[i][2]); o.w = tf32_rna(acc[i][3]);
        *(float4*)(g_Wh + (size_t)m * HD + n0 + tcol * 4) = o;
    }

    #pragma unroll
    for (int i = 0; i < 4; i++) {
        float s = acc[i][0]*acc[i][0] + acc[i][1]*acc[i][1]
                + acc[i][2]*acc[i][2] + acc[i][3]*acc[i][3];
        esh[trow*4 + i][tcol] = s;
    }
    __syncthreads();
    if (t < 64) {
        float s = 0.f;
        #pragma unroll
        for (int j = 0; j < 16; j++) s += esh[t][j];
        g_e[(size_t)(m0 + t) * HEADS + (n0 >> 6)] = s;
    }
}

// ============================================================
// Kernel B1: per-(b,h) softmax stats — 32 blocks
// ============================================================
__global__ __launch_bounds__(256) void k_stats() {
    const int b = blockIdx.x >> 2;
    const int h = blockIdx.x & 3;
    const int t = threadIdx.x;
    __shared__ float red[256];

    const float* eb = g_e + (size_t)b * NNODES * HEADS;

    float mx = -1e30f;
    for (int n = t; n < NNODES; n += 256)
        mx = fmaxf(mx, eb[n * HEADS + h]);
    red[t] = mx; __syncthreads();
    for (int s = 128; s > 0; s >>= 1) {
        if (t < s) red[t] = fmaxf(red[t], red[t + s]);
        __syncthreads();
    }
    mx = red[0]; __syncthreads();

    float sum = 0.f;
    for (int n = t; n < NNODES; n += 256)
        sum += __expf(eb[n * HEADS + h] - mx);
    red[t] = sum; __syncthreads();
    for (int s = 128; s > 0; s >>= 1) {
        if (t < s) red[t] += red[t + s];
        __syncthreads();
    }
    if (t == 0) {
        g_mx[blockIdx.x]  = mx;
        g_inv[blockIdx.x] = 1.0f / red[0];
    }
}

// ============================================================
// Kernel B2: att = head-mean of softmax — 64 blocks
// ============================================================
__global__ __launch_bounds__(256) void k_att() {
    int m = blockIdx.x * 256 + threadIdx.x;
    if (m >= MTOT) return;
    int b = m >> 11;
    const float* e4 = g_e + (size_t)m * HEADS;
    float a = 0.f;
    #pragma unroll
    for (int h = 0; h < HEADS; h++)
        a += __expf(e4[h] - g_mx[b * HEADS + h]) * g_inv[b * HEADS + h];
    g_att[m] = 0.25f * a;
}

// ============================================================
// Kernel C: tf32 mma.sync GEMM, BIG warp tiles for ILP
//   out = relu(att*(adj @ Wh) + bias)
// BM=128, BN=128, BK=32, 8 warps (4m x 2n), warp tile 32x64
// A [128][36] (bank 4r+kk conflict-free), B [32][136] (bank 8kk+q conflict-free)
// 2 CTAs/SM (regs capped 128, smem 2x71.7KB), 256 CTAs = 1 wave
// ============================================================
#define A_LD   36
#define B_LD   136
#define B_OFF  18432                 // 128*36*4
#define STAGE  35840                 // 18432 + 32*136*4

__global__ void __launch_bounds__(256, 2)
k_out_tf32(const float* __restrict__ adj, const float* __restrict__ bias,
           float* __restrict__ out) {
    extern __shared__ char smem[];
    const uint32_t sb = smem_u32(smem);
    const int t    = threadIdx.x;
    const int lane = t & 31;
    const int wid  = t >> 5;
    const int b    = blockIdx.z;
    const int n0   = blockIdx.x * 128;   // n fastest -> adj tile L2 reuse
    const int m0   = blockIdx.y * 128;
    const int warp_m = wid & 3;          // 32 rows
    const int warp_n = wid >> 2;         // 64 cols

    const float* adjb = adj + (size_t)b * NNODES * NNODES;
    const float* Whb  = g_Wh + ((size_t)b * NNODES) * HD;

    float c[2][8][4];
    #pragma unroll
    for (int mt = 0; mt < 2; mt++)
        #pragma unroll
        for (int nt = 0; nt < 8; nt++)
            #pragma unroll
            for (int j = 0; j < 4; j++) c[mt][nt][j] = 0.f;

    auto load_stage = [&](int k0, uint32_t dst) {
        #pragma unroll
        for (int it = 0; it < 4; it++) {        // A: 128x32 = 1024 chunks of 16B
            int idx = t + it * 256;
            int row = idx >> 3, u = idx & 7;
            CPASYNC16CG(dst + row * (A_LD*4) + u * 16,
                        adjb + (size_t)(m0 + row) * NNODES + k0 + u * 4);
        }
        #pragma unroll
        for (int it = 0; it < 4; it++) {        // B: 32x128 = 1024 chunks of 16B
            int idx = t + it * 256;
            int row = idx >> 5, u = idx & 31;
            CPASYNC16CG(dst + B_OFF + row * (B_LD*4) + u * 16,
                        Whb + (size_t)(k0 + row) * HD + n0 + u * 4);
        }
        CPCOMMIT();
    };

    load_stage(0, sb);
    CPWAIT0();
    __syncthreads();

    for (int i = 0; i < 64; i++) {
        const uint32_t cur = (uint32_t)(i & 1) * STAGE;
        if (i < 63) load_stage((i + 1) * 32, sb + (uint32_t)((i + 1) & 1) * STAGE);

        const float* Asm = (const float*)(smem + cur);
        const float* Bsm = (const float*)(smem + cur + B_OFF);

        #pragma unroll
        for (int s = 0; s < 4; s++) {
            const int kk = s * 8 + (lane & 3);
            uint32_t a[2][4];
            #pragma unroll
            for (int mt = 0; mt < 2; mt++) {
                int r = warp_m * 32 + mt * 16 + (lane >> 2);
                a[mt][0] = __float_as_uint(Asm[r * A_LD + kk]);        // raw bits: HW tf32 trunc
                a[mt][1] = __float_as_uint(Asm[(r + 8) * A_LD + kk]);
                a[mt][2] = __float_as_uint(Asm[r * A_LD + kk + 4]);
                a[mt][3] = __float_as_uint(Asm[(r + 8) * A_LD + kk + 4]);
            }
            #pragma unroll
            for (int ng = 0; ng < 8; ng++) {
                int n = warp_n * 64 + ng * 8 + (lane >> 2);
                uint32_t b0 = __float_as_uint(Bsm[kk * B_LD + n]);     // pre-rounded (RNA)
                uint32_t b1 = __float_as_uint(Bsm[(kk + 4) * B_LD + n]);
                MMA1688(c[0][ng], a[0], b0, b1);
                MMA1688(c[1][ng], a[1], b0, b1);
            }
        }

        if (i < 63) { CPWAIT0(); __syncthreads(); }
    }

    #pragma unroll
    for (int mt = 0; mt < 2; mt++) {
        int r0 = m0 + warp_m * 32 + mt * 16 + (lane >> 2);
        float att0 = g_att[b * NNODES + r0];
        float att1 = g_att[b * NNODES + r0 + 8];
        float* o0 = out + ((size_t)(b * NNODES + r0)) * HD;
        float* o1 = o0 + (size_t)8 * HD;
        #pragma unroll
        for (int nt = 0; nt < 8; nt++) {
            int col = n0 + warp_n * 64 + nt * 8 + 2 * (lane & 3);
            float2 bv = *(const float2*)(bias + col);
            float2 v0, v1;
            v0.x = fmaxf(fmaf(att0, c[mt][nt][0], bv.x), 0.f);
            v0.y = fmaxf(fmaf(att0, c[mt][nt][1], bv.y), 0.f);
            v1.x = fmaxf(fmaf(att1, c[mt][nt][2], bv.x), 0.f);
            v1.y = fmaxf(fmaf(att1, c[mt][nt][3], bv.y), 0.f);
            *(float2*)(o0 + col) = v0;
            *(float2*)(o1 + col) = v1;
        }
    }
}

// ============================================================
extern "C" void kernel_launch(void* const* d_in, const int* in_sizes, int n_in,
                              void* d_out, int out_size) {
    const float* features = (const float*)d_in[0];   // [8,2048,256]
    const float* adj      = (const float*)d_in[1];   // [8,2048,2048]
    const float* W        = (const float*)d_in[2];   // [256,256]
    const float* bias     = (const float*)d_in[3];   // [256]
    float* out = (float*)d_out;                      // [8,2048,256]

    cudaFuncSetAttribute(k_out_tf32, cudaFuncAttributeMaxDynamicSharedMemorySize, 2 * STAGE);

    k_wh      <<<dim3(HD/64, MTOT/64), 256>>>(features, W);
    k_stats   <<<BATCH*HEADS, 256>>>();
    k_att     <<<MTOT/256, 256>>>();
    k_out_tf32<<<dim3(HD/128, NNODES/128, BATCH), 256, 2 * STAGE>>>(adj, bias, out);
}